// round 6
// baseline (speedup 1.0000x reference)
#include <cuda_runtime.h>
#include <cuda_bf16.h>

#define NBINS 100
#define NROWS 102          // guard rows: j in [0,100] -> rows j and j+1
#define EPSF  1e-10f
#define COLS  32
#define GRID_BLOCKS 1216   // 152 SMs * 8 blocks
#define DEPTH 8            // float4-pairs in flight per thread (16 LDG.128)

__device__ float        g_hist[NBINS];
__device__ float        g_wss[NBINS];
__device__ unsigned int g_count;

typedef unsigned long long u64;

__device__ __forceinline__ u64 pack2(float lo, float hi) {
    u64 r; asm("mov.b64 %0, {%1, %2};" : "=l"(r) : "f"(lo), "f"(hi)); return r;
}
__device__ __forceinline__ u64 addf32x2(u64 a, u64 b) {
    u64 r; asm("add.rn.f32x2 %0, %1, %2;" : "=l"(r) : "l"(a), "l"(b)); return r;
}

struct Contrib {
    int j;       // row for P; S goes to row j+1
    u64 P;       // (wp, wp^2) packed
    u64 S;       // (ws, ws^2) packed
};

// No validity predicates: accumulate always; readout masks rows to [1,98].
__device__ __forceinline__ Contrib elem_contrib(float of, float wf,
                                                float invd, float nb0)
{
    Contrib c;
    float t  = fmaf(of, invd, nb0);      // (of - b0) * invd, >= 0 for valid input
    float jf = floorf(t);
    float fr = t - jf;
    int   j  = (int)jf;
    c.j      = min(max(j, 0), NROWS - 2);
    float frw = fr * wf;
    float wp  = wf - frw;                // (1 - fr) * wf
    c.P = pack2(wp,  wp * wp);
    c.S = pack2(frw, frw * frw);
    return c;
}

// Batched 2-element RMW with collision merge (|dj|<=1) so all 4 LDS precede STS.
__device__ __forceinline__ void pair_rmw(u64* __restrict__ shl,
                                         Contrib a, Contrib b)
{
    int d = b.j - a.j;
    bool m0 = (d == 0), mp = (d == 1), mm = (d == -1);
    u64 addP = m0 ? a.P : (mp ? a.S : 0ULL);
    u64 addS = m0 ? a.S : (mm ? a.P : 0ULL);
    b.P = addf32x2(b.P, addP);
    b.S = addf32x2(b.S, addS);
    u64 aP = (m0 | mm) ? 0ULL : a.P;
    u64 aS = (m0 | mp) ? 0ULL : a.S;

    u64* pa = shl + a.j * COLS;
    u64* pb = shl + b.j * COLS;
    u64 la0 = pa[0], la1 = pa[COLS];
    u64 lb0 = pb[0], lb1 = pb[COLS];
    la0 = addf32x2(la0, aP);
    la1 = addf32x2(la1, aS);
    lb0 = addf32x2(lb0, b.P);
    lb1 = addf32x2(lb1, b.S);
    pa[0]    = la0;
    pa[COLS] = la1;
    pb[0]    = lb0;   // b-stores last: overwrite merged cells correctly
    pb[COLS] = lb1;
}

__device__ __forceinline__ void process4(u64* __restrict__ shl,
                                         float4 o, float4 w,
                                         float invd, float nb0)
{
    Contrib c0 = elem_contrib(o.x, w.x, invd, nb0);
    Contrib c1 = elem_contrib(o.y, w.y, invd, nb0);
    Contrib c2 = elem_contrib(o.z, w.z, invd, nb0);
    Contrib c3 = elem_contrib(o.w, w.w, invd, nb0);
    pair_rmw(shl, c0, c1);
    pair_rmw(shl, c2, c3);
}

__global__ __launch_bounds__(32, 8) void fused_k(
    const float4* __restrict__ obs4,
    const float4* __restrict__ wts4,
    const float*  __restrict__ obs_s,
    const float*  __restrict__ wts_s,
    const float*  __restrict__ bins,
    const float*  __restrict__ histo_exp,
    float*        __restrict__ out,
    int nvec, int n)
{
    __shared__ u64 sh[NROWS * COLS];   // cell = packed (hist, wss); lane-private cols
    const int lane = threadIdx.x;

    #pragma unroll
    for (int i = lane; i < NROWS * COLS; i += 32)
        sh[i] = 0ULL;
    __syncwarp();

    const float b0   = __ldg(&bins[0]);
    const float bN   = __ldg(&bins[NBINS]);
    const float invd = (float)NBINS / (bN - b0);
    const float nb0  = -b0 * invd;

    u64* shl = &sh[lane];
    const int stride = GRID_BLOCKS * 32;
    const int base   = blockIdx.x * 32 + lane;

    // Deep rotating prefetch pipeline; OOB slots load clamped index with w=0.
    float4 O[DEPTH], W[DEPTH];
    #pragma unroll
    for (int d = 0; d < DEPTH; d++) {
        int vi   = base + d * stride;
        bool act = vi < nvec;
        int idx  = act ? vi : (nvec - 1);
        O[d] = obs4[idx];
        float4 ww = wts4[idx];
        if (!act) ww = make_float4(0.0f, 0.0f, 0.0f, 0.0f);
        W[d] = ww;
    }

    for (int v = base; v < nvec; v += DEPTH * stride) {
        #pragma unroll
        for (int d = 0; d < DEPTH; d++) {
            int vi   = v + (DEPTH + d) * stride;
            bool act = vi < nvec;
            int idx  = act ? vi : (nvec - 1);
            float4 no = obs4[idx];
            float4 nw = wts4[idx];
            process4(shl, O[d], W[d], invd, nb0);
            O[d] = no;
            W[d] = act ? nw : make_float4(0.0f, 0.0f, 0.0f, 0.0f);
        }
    }

    // Scalar tail (N % 4), block 0 only (empty for N = 2^25).
    if (blockIdx.x == 0) {
        for (int i = nvec * 4 + lane; i < n; i += 32) {
            Contrib c = elem_contrib(obs_s[i], wts_s[i], invd, nb0);
            u64* p = shl + c.j * COLS;
            p[0]    = addf32x2(p[0],    c.P);
            p[COLS] = addf32x2(p[COLS], c.S);
        }
    }
    __syncwarp();

    // Conflict-free rotated per-row reduction; rows [1,98] map to bins.
    const float2* shf = (const float2*)sh;
    #pragma unroll
    for (int g = 0; g < 4; g++) {
        int r = g * 32 + lane;
        if (r < NROWS) {
            float h = 0.0f, s = 0.0f;
            #pragma unroll
            for (int t = 0; t < 32; t++) {
                int c = (lane + t) & 31;
                float2 vv = shf[r * COLS + c];
                h += vv.x; s += vv.y;
            }
            if (r >= 1 && r <= NBINS - 2) {
                atomicAdd(&g_hist[r], h);
                atomicAdd(&g_wss[r], s);
            }
        }
    }

    // Last-block-done: final chi^2 + reset for next graph replay.
    __syncwarp();
    __threadfence();
    unsigned int done = 0;
    if (lane == 0) done = atomicAdd(&g_count, 1u);
    done = __shfl_sync(0xFFFFFFFFu, done, 0);
    if (done == (unsigned)(GRID_BLOCKS - 1)) {
        __threadfence();
        float hs[4], ss[4], he[4];
        float hsum = 0.0f, esum = 0.0f;
        #pragma unroll
        for (int g = 0; g < 4; g++) {
            int b = g * 32 + lane;
            bool ok = (b < NBINS);
            hs[g] = ok ? __ldcg(&g_hist[b]) : 0.0f;
            ss[g] = ok ? __ldcg(&g_wss[b])  : 0.0f;
            he[g] = ok ? __ldg(&histo_exp[b]) : 0.0f;
            hsum += hs[g];
            esum += he[g];
        }
        #pragma unroll
        for (int o = 16; o > 0; o >>= 1) {
            hsum += __shfl_xor_sync(0xFFFFFFFFu, hsum, o);
            esum += __shfl_xor_sync(0xFFFFFFFFu, esum, o);
        }
        const float inv_ss2 = 1.0f / ((hsum + EPSF) * (hsum + EPSF));
        const float inv_se2 = 1.0f / ((esum + EPSF) * (esum + EPSF));
        const float inv_ss  = 1.0f / hsum;
        const float inv_se  = 1.0f / esum;
        float chi = 0.0f;
        #pragma unroll
        for (int g = 0; g < 4; g++) {
            int b = g * 32 + lane;
            if (b < NBINS) {
                float unc_sim = ss[g] * inv_ss2 + EPSF;
                float unc_exp = he[g] * (1.0f - he[g] * inv_se) * inv_se2 + EPSF;
                float d = hs[g] * inv_ss - he[g] * inv_se;
                chi += d * d / (unc_sim + unc_exp);
            }
        }
        #pragma unroll
        for (int o = 16; o > 0; o >>= 1)
            chi += __shfl_xor_sync(0xFFFFFFFFu, chi, o);
        if (lane == 0) out[0] = chi;

        #pragma unroll
        for (int g = 0; g < 4; g++) {
            int b = g * 32 + lane;
            if (b < NBINS) {
                __stcg(&g_hist[b], 0.0f);
                __stcg(&g_wss[b], 0.0f);
            }
        }
        __threadfence();
        if (lane == 0) atomicExch(&g_count, 0u);
    }
}

extern "C" void kernel_launch(void* const* d_in, const int* in_sizes, int n_in,
                              void* d_out, int out_size) {
    const float* sim  = (const float*)d_in[0];
    // d_in[1] = exp_observable: unused in the fixed_binning branch
    const float* wts  = (const float*)d_in[2];
    const float* bins = (const float*)d_in[3];
    const float* he   = (const float*)d_in[4];
    int n    = in_sizes[0];
    int nvec = n / 4;

    cudaFuncSetAttribute(fused_k, cudaFuncAttributePreferredSharedMemoryCarveout, 100);

    fused_k<<<GRID_BLOCKS, 32>>>((const float4*)sim, (const float4*)wts,
                                 sim, wts, bins, he, (float*)d_out, nvec, n);
}